// round 14
// baseline (speedup 1.0000x reference)
#include <cuda_runtime.h>
#include <cuda_bf16.h>

// SE block: B=32, H=W=56 (HW=3136), C=256, R=16
#define HW      3136
#define CCH     256
#define NB      32
#define NS      49               // 64-row units per batch
#define CHUNK   64
#define HB      16               // batches per half
#define HUNITS  (HB * NS)        // 784 units per half
#define NBLK    784              // one block per unit per phase (perfect balance)

// Scratch (__device__ globals; zero-init; self-resetting)
__device__ float g_partial[NB * NS * CCH];   // [b][s][c]
__device__ float g_gate[NB * CCH];
__device__ unsigned g_done[NB];              // per-batch pool counters
__device__ unsigned g_count = 0;             // barrier arrivals
__device__ unsigned g_gen   = 0;             // barrier generation

__device__ __forceinline__ void grid_barrier() {
    __syncthreads();
    if (threadIdx.x == 0) {
        unsigned gen = *((volatile unsigned*)&g_gen);
        __threadfence();
        if (atomicAdd(&g_count, 1u) == NBLK - 1) {
            g_count = 0;
            __threadfence();
            atomicAdd(&g_gen, 1u);
        } else {
            while (*((volatile unsigned*)&g_gen) == gen) { }
        }
        __threadfence();
    }
    __syncthreads();
}

struct SMem {
    float4 red[256];
    float  s_s[CCH];
    float  s_h[16];
    float  s_w1[CCH * 16];
    int    flag;
};

// Pool 64-row unit u of half h; block completing batch b runs its MLP inline.
__device__ __forceinline__ void pool_unit(int h, int u, int t, int c4, int ho,
                                          const float4* __restrict__ x4,
                                          const float* __restrict__ w1,
                                          const float* __restrict__ b1,
                                          const float* __restrict__ w2,
                                          const float* __restrict__ b2,
                                          SMem* sm) {
    const int b = h * HB + u / NS, s = u - (u / NS) * NS;
    const size_t base = ((size_t)b * HW + (size_t)s * CHUNK + ho) * (CCH / 4) + c4;

    float4 acc = make_float4(0.f, 0.f, 0.f, 0.f);
#pragma unroll
    for (int k = 0; k < CHUNK; k += 4) {
        float4 vv = x4[base + (size_t)k * (CCH / 4)];
        acc.x += vv.x; acc.y += vv.y; acc.z += vv.z; acc.w += vv.w;
    }
    sm->red[t] = acc;
    __syncthreads();
    if (t < 64) {
        float4 a = sm->red[t], e = sm->red[t + 64], f = sm->red[t + 128], hh = sm->red[t + 192];
        float4 r = make_float4(a.x + e.x + f.x + hh.x,
                               a.y + e.y + f.y + hh.y,
                               a.z + e.z + f.z + hh.z,
                               a.w + e.w + f.w + hh.w);
        reinterpret_cast<float4*>(g_partial)[((size_t)b * NS + s) * (CCH / 4) + t] = r;
    }
    __syncthreads();
    if (t == 0) {
        __threadfence();                       // release partial stores (t0-only)
        unsigned old = atomicAdd(&g_done[b], 1u);
        sm->flag = (old == NS - 1);
        if (sm->flag) __threadfence();         // acquire peers' partials
    }
    __syncthreads();
    if (!sm->flag) return;

    // ---- inline excitation MLP for batch b ----
    if (t == 0) g_done[b] = 0;                 // reset for next replay
#pragma unroll
    for (int i = t; i < CCH * 16; i += 256) sm->s_w1[i] = w1[i];

    float accm = 0.f;
#pragma unroll 7
    for (int ss = 0; ss < NS; ss++)
        accm += __ldcg(&g_partial[((size_t)b * NS + ss) * CCH + t]);
    sm->s_s[t] = accm * (1.0f / (float)HW);
    __syncthreads();

    {   // dense1: t = grp*16 + cout
        const int cout = t & 15;
        const int grp  = t >> 4;
        float p = 0.f;
#pragma unroll
        for (int k = grp * 16; k < grp * 16 + 16; k++)
            p = fmaf(sm->s_s[k], sm->s_w1[k * 16 + cout], p);
        reinterpret_cast<float*>(sm->red)[t] = p;
    }
    __syncthreads();
    if (t < 16) {
        float hd = b1[t];
#pragma unroll
        for (int j = 0; j < 16; j++)
            hd += reinterpret_cast<float*>(sm->red)[j * 16 + t];
        sm->s_h[t] = fmaxf(hd, 0.f);
    }
    __syncthreads();

    float g = b2[t];
#pragma unroll
    for (int j = 0; j < 16; j++)
        g = fmaf(sm->s_h[j], w2[j * CCH + t], g);
    g_gate[b * CCH + t] = 1.f / (1.f + __expf(-g));   // visible after next grid_barrier
    __syncthreads();
}

template <bool STREAMING>
__device__ __forceinline__ void scale_unit(int h, int u, int t, int c4, int ho,
                                           const float4* __restrict__ x4,
                                           float4* __restrict__ o4) {
    const int b = h * HB + u / NS, s = u - (u / NS) * NS;
    const float4 g = reinterpret_cast<const float4*>(g_gate)[b * (CCH / 4) + c4];
    const size_t base = ((size_t)b * HW + (size_t)s * CHUNK + ho) * (CCH / 4) + c4;
#pragma unroll
    for (int k = 0; k < CHUNK; k += 4) {
        const size_t idx = base + (size_t)k * (CCH / 4);
        float4 vv = x4[idx];                   // L2 hit (pooled last phase)
        vv.x *= g.x; vv.y *= g.y; vv.z *= g.z; vv.w *= g.w;
        if (STREAMING) __stcs(&o4[idx], vv);   // phase B: keep L2 for x
        else           o4[idx] = vv;           // phase C: lazy write-back drain
    }
}

__global__ void __launch_bounds__(256, 6)
k_se(const float* __restrict__ x,
     const float* __restrict__ w1,
     const float* __restrict__ b1,
     const float* __restrict__ w2,
     const float* __restrict__ b2,
     float* __restrict__ out) {
    const int bid = blockIdx.x;
    const int t   = threadIdx.x;
    const int c4  = t & 63;
    const int ho  = t >> 6;

    const float4* x4 = reinterpret_cast<const float4*>(x);
    float4*       o4 = reinterpret_cast<float4*>(out);

    __shared__ SMem sm;

    // ---- Phase A: pool half A (one unit per block; inline MLPs) ----
    pool_unit(0, bid, t, c4, ho, x4, w1, b1, w2, b2, &sm);

    grid_barrier();   // gates(A) ready; x(A) resident in L2

    // ---- Phase B: duplex — even blocks read-then-write, odd write-then-read ----
    if (bid & 1) {
        scale_unit<true>(0, bid, t, c4, ho, x4, o4);
        pool_unit(1, bid, t, c4, ho, x4, w1, b1, w2, b2, &sm);
    } else {
        pool_unit(1, bid, t, c4, ho, x4, w1, b1, w2, b2, &sm);
        scale_unit<true>(0, bid, t, c4, ho, x4, o4);
    }

    grid_barrier();   // gates(B) ready; x(B) resident in L2

    // ---- Phase C: scale half B ----
    scale_unit<false>(1, bid, t, c4, ho, x4, o4);
}

extern "C" void kernel_launch(void* const* d_in, const int* in_sizes, int n_in,
                              void* d_out, int out_size) {
    const float* x  = (const float*)d_in[0];
    const float* w1 = (const float*)d_in[1];
    const float* b1 = (const float*)d_in[2];
    const float* w2 = (const float*)d_in[3];
    const float* b2 = (const float*)d_in[4];
    float* out = (float*)d_out;

    k_se<<<NBLK, 256>>>(x, w1, b1, w2, b2, out);
}

// round 15
// speedup vs baseline: 2.0400x; 2.0400x over previous
#include <cuda_runtime.h>
#include <cuda_bf16.h>

// SE block: B=32, H=W=56 (HW=3136), C=256, R=16
#define HW     3136
#define CCH    256
#define NB     32
#define NS     49              // hw chunks per batch
#define CHUNK  64              // hw rows per unit
#define NUNIT  (NB * NS)       // 1568 units, u = b*49 + s
#define NBLK   592             // 148 SMs * 4 blocks, all co-resident (validated)

// Scratch (__device__ globals; zero-init; self-resetting per launch)
__device__ float g_partial[NUNIT * CCH];   // [u][c]
__device__ float g_gate[NB * CCH];
__device__ unsigned g_done[NB];            // per-batch pool-completion counters
__device__ unsigned g_count = 0;           // barrier arrivals
__device__ unsigned g_gen   = 0;           // barrier generation

__device__ __forceinline__ void grid_barrier() {
    __syncthreads();
    if (threadIdx.x == 0) {
        unsigned gen = *((volatile unsigned*)&g_gen);
        __threadfence();
        if (atomicAdd(&g_count, 1u) == NBLK - 1) {
            g_count = 0;
            __threadfence();
            atomicAdd(&g_gen, 1u);
        } else {
            while (*((volatile unsigned*)&g_gen) == gen) { }
        }
        __threadfence();
    }
    __syncthreads();
}

struct SMem {
    float4 red[256];        // pool reduction / MLP partials
    float  s_s[CCH];
    float  s_h[16];
    float  s_w1[CCH * 16];
    int    flag;
};

__global__ void __launch_bounds__(256, 4)
k_se(const float* __restrict__ x,
     const float* __restrict__ w1,
     const float* __restrict__ b1,
     const float* __restrict__ w2,
     const float* __restrict__ b2,
     float* __restrict__ out) {
    const int bid = blockIdx.x;
    const int t   = threadIdx.x;
    const int c4  = t & 63;        // float4 channel group
    const int ho  = t >> 6;        // hw sub-offset 0..3

    const float4* x4 = reinterpret_cast<const float4*>(x);
    float4*       o4 = reinterpret_cast<float4*>(out);

    __shared__ SMem sm;

    // ---------------- Phase 1: pooling, MLP inlined on batch completion ----------------
    for (int u = bid; u < NUNIT; u += NBLK) {
        const int b = u / NS, s = u - b * NS;
        const float4* xp = x4 + ((size_t)b * HW + (size_t)s * CHUNK + ho) * (CCH / 4) + c4;

        float4 acc = make_float4(0.f, 0.f, 0.f, 0.f);
#pragma unroll
        for (int k = 0; k < CHUNK; k += 4) {
            float4 v = xp[(size_t)k * (CCH / 4)];
            acc.x += v.x; acc.y += v.y; acc.z += v.z; acc.w += v.w;
        }
        sm.red[t] = acc;
        __syncthreads();
        if (t < 64) {
            float4 a = sm.red[t], e = sm.red[t + 64], f = sm.red[t + 128], h = sm.red[t + 192];
            float4 r = make_float4(a.x + e.x + f.x + h.x,
                                   a.y + e.y + f.y + h.y,
                                   a.z + e.z + f.z + h.z,
                                   a.w + e.w + f.w + h.w);
            reinterpret_cast<float4*>(g_partial)[(size_t)u * (CCH / 4) + t] = r;
        }
        __syncthreads();
        if (t == 0) {
            __threadfence();                    // release partials (t0-only, post-bar)
            unsigned old = atomicAdd(&g_done[b], 1u);
            sm.flag = (old == NS - 1);
            if (sm.flag) __threadfence();       // acquire peers' partials
        }
        __syncthreads();

        if (sm.flag) {
            // ---- inline excitation MLP for batch b (hidden under other blocks' pooling) ----
            if (t == 0) g_done[b] = 0;          // reset for next graph replay
#pragma unroll
            for (int i = t; i < CCH * 16; i += 256) sm.s_w1[i] = w1[i];

            float accm = 0.f;
#pragma unroll
            for (int ss = 0; ss < NS; ss++)
                accm += __ldcg(&g_partial[((size_t)b * NS + ss) * CCH + t]);
            sm.s_s[t] = accm * (1.0f / (float)HW);
            __syncthreads();

            {   // dense1 parallelized: t = grp*16 + cout
                const int cout = t & 15;
                const int grp  = t >> 4;
                float p = 0.f;
#pragma unroll
                for (int k = grp * 16; k < grp * 16 + 16; k++)
                    p = fmaf(sm.s_s[k], sm.s_w1[k * 16 + cout], p);
                reinterpret_cast<float*>(sm.red)[t] = p;
            }
            __syncthreads();
            if (t < 16) {
                float h = b1[t];
#pragma unroll
                for (int j = 0; j < 16; j++)
                    h += reinterpret_cast<float*>(sm.red)[j * 16 + t];
                sm.s_h[t] = fmaxf(h, 0.f);
            }
            __syncthreads();

            float g = b2[t];
#pragma unroll
            for (int j = 0; j < 16; j++)
                g = fmaf(sm.s_h[j], w2[j * CCH + t], g);
            g_gate[b * CCH + t] = 1.f / (1.f + __expf(-g));  // visible after grid_barrier
            __syncthreads();
        }
    }

    grid_barrier();   // single barrier: all gates published; x hot in L2

    // ---------------- Phase 2: broadcast multiply, REVERSE order (R11) ----------------
    const int u_last = bid + ((NUNIT - 1 - bid) / NBLK) * NBLK;
    for (int u = u_last; u >= 0; u -= NBLK) {
        const int b = u / NS, s = u - b * NS;
        const size_t base = ((size_t)b * HW + (size_t)s * CHUNK + ho) * (CCH / 4) + c4;

        const float4 g = reinterpret_cast<const float4*>(g_gate)[b * (CCH / 4) + c4];

#pragma unroll
        for (int k = 0; k < CHUNK; k += 4) {
            const size_t idx = base + (size_t)k * (CCH / 4);
            float4 v = x4[idx];          // L2 hit (pooled this launch, reverse recency)
            v.x *= g.x; v.y *= g.y; v.z *= g.z; v.w *= g.w;
            o4[idx] = v;                 // write-back: lazy DRAM drain (R11 win)
        }
    }
}

extern "C" void kernel_launch(void* const* d_in, const int* in_sizes, int n_in,
                              void* d_out, int out_size) {
    const float* x  = (const float*)d_in[0];
    const float* w1 = (const float*)d_in[1];
    const float* b1 = (const float*)d_in[2];
    const float* w2 = (const float*)d_in[3];
    const float* b2 = (const float*)d_in[4];
    float* out = (float*)d_out;

    k_se<<<NBLK, 256>>>(x, w1, b1, w2, b2, out);
}

// round 16
// speedup vs baseline: 2.2007x; 1.0788x over previous
#include <cuda_runtime.h>
#include <cuda_bf16.h>

// SE block: B=32, H=W=56 (HW=3136), C=256, R=16
#define HW     3136
#define CCH    256
#define NB     32
#define NS     49              // hw chunks per batch
#define CHUNK  64              // hw rows per unit
#define NUNIT  (NB * NS)       // 1568 units, u = b*49 + s
#define NBLK   592             // 148 SMs * 4 blocks, co-resident (validated)
#define KTICK  (NUNIT + NBLK)  // 2160 draws per phase (NUNIT work + NBLK exits), exact

// Scratch (__device__ globals per allocation-free rule)
__device__ float g_partial[NUNIT * CCH];   // [u][c]
__device__ float g_gate[NB * CCH];
__device__ unsigned g_tick  = 0;           // monotonic ticket counter (never reset)
__device__ unsigned g_count = 0;           // barrier arrivals (self-resetting)
__device__ unsigned g_gen   = 0;           // barrier generation (monotonic)

__device__ __forceinline__ void grid_barrier() {
    __syncthreads();
    if (threadIdx.x == 0) {
        unsigned gen = *((volatile unsigned*)&g_gen);
        __threadfence();
        if (atomicAdd(&g_count, 1u) == NBLK - 1) {
            g_count = 0;
            __threadfence();
            atomicAdd(&g_gen, 1u);
        } else {
            while (*((volatile unsigned*)&g_gen) == gen) { }
        }
        __threadfence();
    }
    __syncthreads();
}

struct SMem {
    float4 red[256];        // pool reduction / MLP partials
    float  s_s[CCH];
    float  s_h[16];
    float  s_w1[CCH * 16];
    int    u;               // broadcast ticket
};

// Draw next work ticket (block-uniform). Valid iff return < NUNIT.
__device__ __forceinline__ int next_ticket(SMem* sm, int t) {
    __syncthreads();                           // protect sm->u from prior readers
    if (t == 0) {
        unsigned raw = atomicAdd(&g_tick, 1u);
        sm->u = (int)(raw % KTICK);            // per-phase windows are exact (see KTICK)
    }
    __syncthreads();
    return sm->u;
}

__global__ void __launch_bounds__(256, 4)
k_se(const float* __restrict__ x,
     const float* __restrict__ w1,
     const float* __restrict__ b1,
     const float* __restrict__ w2,
     const float* __restrict__ b2,
     float* __restrict__ out) {
    const int bid = blockIdx.x;
    const int t   = threadIdx.x;
    const int c4  = t & 63;        // float4 channel group
    const int ho  = t >> 6;        // hw sub-offset 0..3

    const float4* x4 = reinterpret_cast<const float4*>(x);
    float4*       o4 = reinterpret_cast<float4*>(out);

    __shared__ SMem sm;

    // ---------------- Phase 1: pooling (ticket-balanced, fence-free) ----------------
    for (;;) {
        const int u = next_ticket(&sm, t);
        if (u >= NUNIT) break;
        const int b = u / NS, s = u - b * NS;
        const float4* xp = x4 + ((size_t)b * HW + (size_t)s * CHUNK + ho) * (CCH / 4) + c4;

        float4 acc = make_float4(0.f, 0.f, 0.f, 0.f);
#pragma unroll
        for (int k = 0; k < CHUNK; k += 4) {
            float4 v = xp[(size_t)k * (CCH / 4)];
            acc.x += v.x; acc.y += v.y; acc.z += v.z; acc.w += v.w;
        }
        sm.red[t] = acc;
        __syncthreads();
        if (t < 64) {
            float4 a = sm.red[t], e = sm.red[t + 64], f = sm.red[t + 128], h = sm.red[t + 192];
            float4 r = make_float4(a.x + e.x + f.x + h.x,
                                   a.y + e.y + f.y + h.y,
                                   a.z + e.z + f.z + h.z,
                                   a.w + e.w + f.w + h.w);
            reinterpret_cast<float4*>(g_partial)[(size_t)u * (CCH / 4) + t] = r;
        }
        // publication handled by the grid barrier below (no per-unit fence — R15 lesson)
    }

    grid_barrier();

    // ---------------- Phase MLP: blocks 0..31, one per batch ----------------
    if (bid < NB) {
        const int b = bid;
#pragma unroll
        for (int i = t; i < CCH * 16; i += 256) sm.s_w1[i] = w1[i];

        float accm = 0.f;
#pragma unroll
        for (int s = 0; s < NS; s++)
            accm += g_partial[((size_t)b * NS + s) * CCH + t];
        sm.s_s[t] = accm * (1.0f / (float)HW);
        __syncthreads();

        {   // dense1 parallelized: t = grp*16 + cout; 16 groups of 16 k each
            const int cout = t & 15;
            const int grp  = t >> 4;
            float p = 0.f;
#pragma unroll
            for (int k = grp * 16; k < grp * 16 + 16; k++)
                p = fmaf(sm.s_s[k], sm.s_w1[k * 16 + cout], p);
            reinterpret_cast<float*>(sm.red)[t] = p;
        }
        __syncthreads();
        if (t < 16) {
            float h = b1[t];
#pragma unroll
            for (int j = 0; j < 16; j++)
                h += reinterpret_cast<float*>(sm.red)[j * 16 + t];
            sm.s_h[t] = fmaxf(h, 0.f);
        }
        __syncthreads();

        float g = b2[t];
#pragma unroll
        for (int j = 0; j < 16; j++)
            g = fmaf(sm.s_h[j], w2[j * CCH + t], g);
        g_gate[b * CCH + t] = 1.f / (1.f + __expf(-g));
    }

    grid_barrier();

    // ------------- Phase 2: broadcast multiply (ticket-balanced, reverse recency) -------------
    for (;;) {
        const int v = next_ticket(&sm, t);
        if (v >= NUNIT) break;
        const int u = NUNIT - 1 - v;           // most-recently-pooled first (L2-hot)
        const int b = u / NS, s = u - b * NS;
        const size_t base = ((size_t)b * HW + (size_t)s * CHUNK + ho) * (CCH / 4) + c4;

        const float4 g = reinterpret_cast<const float4*>(g_gate)[b * (CCH / 4) + c4];

#pragma unroll
        for (int k = 0; k < CHUNK; k += 4) {
            const size_t idx = base + (size_t)k * (CCH / 4);
            float4 v4 = x4[idx];               // L2 hit (reverse recency)
            v4.x *= g.x; v4.y *= g.y; v4.z *= g.z; v4.w *= g.w;
            o4[idx] = v4;                      // write-back: lazy DRAM drain (R11 win)
        }
    }
}

extern "C" void kernel_launch(void* const* d_in, const int* in_sizes, int n_in,
                              void* d_out, int out_size) {
    const float* x  = (const float*)d_in[0];
    const float* w1 = (const float*)d_in[1];
    const float* b1 = (const float*)d_in[2];
    const float* w2 = (const float*)d_in[3];
    const float* b2 = (const float*)d_in[4];
    float* out = (float*)d_out;

    k_se<<<NBLK, 256>>>(x, w1, b1, w2, b2, out);
}